// round 5
// baseline (speedup 1.0000x reference)
#include <cuda_runtime.h>
#include <math.h>
#include <stdint.h>

#define BB 16
#define NN 2048
#define DD 768
#define WPR (2 * DD)            // words per row in g_hl (hi/lo interleaved)
#define NCHUNK (DD / 8)         // 96 k-chunks of 8
#define NTI 16                  // 128-wide tiles per dim
#define NPART 16

// ---- scratch (no dynamic allocation allowed) ----
__device__ float g_hl[(size_t)BB * NN * WPR];    // tf32 hi/lo interleaved, 192 MB
__device__ float g_sim[(size_t)BB * NN * NN];    // similarity, 256 MB
__device__ float g_part[(size_t)BB * NN * NPART];
__device__ float g_rowsum[BB * NN];
__device__ int   g_order[BB * NN];

__device__ __forceinline__ float tf32_rna(float x) {
    uint32_t u;
    asm("cvt.rna.tf32.f32 %0, %1;" : "=r"(u) : "f"(x));
    return __uint_as_float(u);
}

__device__ __forceinline__ void mma_tf32(float* c, uint32_t a0, uint32_t a1,
                                         uint32_t a2, uint32_t a3,
                                         uint32_t b0, uint32_t b1) {
    asm volatile(
        "mma.sync.aligned.m16n8k8.row.col.f32.tf32.tf32.f32 "
        "{%0,%1,%2,%3}, {%4,%5,%6,%7}, {%8,%9}, {%0,%1,%2,%3};"
        : "+f"(c[0]), "+f"(c[1]), "+f"(c[2]), "+f"(c[3])
        : "r"(a0), "r"(a1), "r"(a2), "r"(a3), "r"(b0), "r"(b1));
}

__device__ __forceinline__ void argmax_combine(float& v, int& i, float v2, int i2) {
    if (v2 > v || (v2 == v && i2 < i)) { v = v2; i = i2; }
}

// ---------------- K1: normalize + tf32 hi/lo split + k-permute ----------------
// k' = (k & ~7) + ((k&3)<<1) + ((k>>2)&1) : within each 8-group, cols (c, c+4)
// land adjacent so one LDS.128 in the GEMM yields (a0hi,a0lo,a2hi,a2lo).
__global__ void knorm(const float* __restrict__ f) {
    const int row = blockIdx.x;
    const float* src = f + (size_t)row * DD;
    float s = 0.f;
    for (int i = threadIdx.x; i < DD; i += 256) { float v = src[i]; s += v * v; }
    for (int o = 16; o; o >>= 1) s += __shfl_down_sync(0xffffffffu, s, o);
    __shared__ float red[8];
    const int w = threadIdx.x >> 5, l = threadIdx.x & 31;
    if (l == 0) red[w] = s;
    __syncthreads();
    if (w == 0) {
        s = (l < 8) ? red[l] : 0.f;
        for (int o = 4; o; o >>= 1) s += __shfl_down_sync(0xffffffffu, s, o);
        if (l == 0) red[0] = 1.0f / fmaxf(sqrtf(s), 1e-12f);
    }
    __syncthreads();
    const float scale = red[0];
    float2* dst = (float2*)(g_hl + (size_t)row * WPR);
    for (int k = threadIdx.x; k < DD; k += 256) {
        const float v = src[k] * scale;
        const float hi = tf32_rna(v);
        const float lo = tf32_rna(v - hi);
        const int kp = (k & ~7) + ((k & 3) << 1) + ((k >> 2) & 1);
        dst[kp] = make_float2(hi, lo);
    }
}

// ---------------- K2: mma.sync tf32 3-pass GEMM + spatial + fused rowsum ----------------
// CTA: 128x128 tile, 256 threads (8 warps, 2x4 grid, 64x32 warp tiles), BK=8,
// double-buffered smem. smem row = 16 words (8 k' x {hi,lo}).
__global__ void __launch_bounds__(256, 2) kgemm(const float* __restrict__ coords) {
    __shared__ float sT[2][4096];      // [stage][ A:128*16 | B:128*16 ]
    __shared__ float2 s_rc[128];
    __shared__ float2 s_cc[128];
    __shared__ float spart[128][4];

    const int tid = threadIdx.x;
    const int wid = tid >> 5, lane = tid & 31;
    const int gid = lane >> 2, lk = lane & 3;
    const int wm = wid >> 2, wn = wid & 3;

    const int nti = blockIdx.x;
    const int b   = blockIdx.z;
    const int tm  = blockIdx.y * 128;
    const int tn  = nti * 128;
    const float* H = g_hl + (size_t)b * NN * WPR;

    {
        const float2* C = (const float2*)(coords + (size_t)b * NN * 2);
        if (tid < 128) s_rc[tid] = C[tm + tid];
        else           s_cc[tid - 128] = C[tn + tid - 128];
    }

    float acc[4][4][4];
#pragma unroll
    for (int mt = 0; mt < 4; mt++)
#pragma unroll
        for (int nt = 0; nt < 4; nt++)
#pragma unroll
            for (int q = 0; q < 4; q++) acc[mt][nt][q] = 0.f;

    // gmem source row for this thread's 4 copy slots
    const float* srcp[4];
    uint32_t dsts[4];
#pragma unroll
    for (int q = 0; q < 4; q++) {
        const int fi = q * 256 + tid;          // 0..1023
        const int r  = fi >> 2;                // 0..255 (A rows then B rows)
        const int seg = fi & 3;
        const int grow = (r < 128) ? (tm + r) : (tn + r - 128);
        srcp[q] = H + (size_t)grow * WPR + seg * 4;
        dsts[q] = r * 16 + seg * 4;
    }

    float4 pf[4];
#pragma unroll
    for (int q = 0; q < 4; q++) pf[q] = *(const float4*)(srcp[q]);
#pragma unroll
    for (int q = 0; q < 4; q++) *(float4*)&sT[0][dsts[q]] = pf[q];
    __syncthreads();

#pragma unroll 1
    for (int c = 0; c < NCHUNK; c++) {
        const int s = c & 1;
        if (c + 1 < NCHUNK) {
#pragma unroll
            for (int q = 0; q < 4; q++) pf[q] = *(const float4*)(srcp[q] + (c + 1) * 16);
        }

        // fragments: A rows wm*64 + mt*16 + gid (+8)
        uint32_t ahi[4][4], alo[4][4];
#pragma unroll
        for (int mt = 0; mt < 4; mt++) {
            const int rb = wm * 64 + mt * 16 + gid;
            const float4 r0 = *(const float4*)&sT[s][rb * 16 + lk * 4];
            const float4 r1 = *(const float4*)&sT[s][(rb + 8) * 16 + lk * 4];
            ahi[mt][0] = __float_as_uint(r0.x); alo[mt][0] = __float_as_uint(r0.y);
            ahi[mt][1] = __float_as_uint(r1.x); alo[mt][1] = __float_as_uint(r1.y);
            ahi[mt][2] = __float_as_uint(r0.z); alo[mt][2] = __float_as_uint(r0.w);
            ahi[mt][3] = __float_as_uint(r1.x == r1.x ? r1.z : r1.z); alo[mt][3] = __float_as_uint(r1.w);
        }
#pragma unroll
        for (int nt = 0; nt < 4; nt++) {
            const int cb = wn * 32 + nt * 8 + gid;
            const float4 rb4 = *(const float4*)&sT[s][2048 + cb * 16 + lk * 4];
            const uint32_t bhi0 = __float_as_uint(rb4.x), blo0 = __float_as_uint(rb4.y);
            const uint32_t bhi1 = __float_as_uint(rb4.z), blo1 = __float_as_uint(rb4.w);
#pragma unroll
            for (int mt = 0; mt < 4; mt++) {
                mma_tf32(acc[mt][nt], ahi[mt][0], ahi[mt][1], ahi[mt][2], ahi[mt][3], bhi0, bhi1);
                mma_tf32(acc[mt][nt], ahi[mt][0], ahi[mt][1], ahi[mt][2], ahi[mt][3], blo0, blo1);
                mma_tf32(acc[mt][nt], alo[mt][0], alo[mt][1], alo[mt][2], alo[mt][3], bhi0, bhi1);
            }
        }

        if (c + 1 < NCHUNK) {
#pragma unroll
            for (int q = 0; q < 4; q++) *(float4*)&sT[s ^ 1][dsts[q]] = pf[q];
        }
        __syncthreads();
    }

    // epilogue: spatial + sim writes + rowsum partials
    float* S = g_sim + (size_t)b * NN * NN;
#pragma unroll
    for (int mt = 0; mt < 4; mt++) {
#pragma unroll
        for (int g2 = 0; g2 < 2; g2++) {
            const int row_l = wm * 64 + mt * 16 + gid + g2 * 8;
            const int grow = tm + row_l;
            const float2 r2 = s_rc[row_l];
            float rs = 0.f;
#pragma unroll
            for (int nt = 0; nt < 4; nt++) {
                const int col_l = wn * 32 + nt * 8 + 2 * lk;
                const float2 c0 = s_cc[col_l];
                const float2 c1 = s_cc[col_l + 1];
                float dx = r2.x - c0.x, dy = r2.y - c0.y;
                const float v0 = acc[mt][nt][2 * g2 + 0] +
                                 0.5f * expf(-(dx * dx + dy * dy) * (1.0f / 10000.0f));
                dx = r2.x - c1.x; dy = r2.y - c1.y;
                const float v1 = acc[mt][nt][2 * g2 + 1] +
                                 0.5f * expf(-(dx * dx + dy * dy) * (1.0f / 10000.0f));
                rs += v0 + v1;
                *(float2*)(S + (size_t)grow * NN + tn + col_l) = make_float2(v0, v1);
            }
            rs += __shfl_xor_sync(0xffffffffu, rs, 1);
            rs += __shfl_xor_sync(0xffffffffu, rs, 2);
            if (lk == 0) spart[row_l][wn] = rs;
        }
    }
    __syncthreads();
    if (tid < 128) {
        const float s4 = spart[tid][0] + spart[tid][1] + spart[tid][2] + spart[tid][3];
        g_part[((size_t)b * NN + tm + tid) * NPART + nti] = s4;
    }
}

// ---------------- K3: reduce partials to row sums ----------------
__global__ void krowsum() {
    const int row = blockIdx.x * 256 + threadIdx.x;
    if (row >= BB * NN) return;
    const float* pp = g_part + (size_t)row * NPART;
    float s = 0.f;
#pragma unroll
    for (int t = 0; t < NPART; t++) s += pp[t];
    g_rowsum[row] = s;
}

// ---------------- K4: greedy traversal, 1 CTA per batch ----------------
__global__ void __launch_bounds__(1024) kgreedy() {
    const int b = blockIdx.x;
    __shared__ unsigned vis[NN / 32];
    __shared__ float sval[32];
    __shared__ int   sidx[32];
    __shared__ int   s_cur;
    const int tid = threadIdx.x;
    const int w = tid >> 5, l = tid & 31;

    if (tid < NN / 32) vis[tid] = 0u;
    __syncthreads();

    {
        const float* rs = g_rowsum + b * NN;
        float v = rs[tid]; int bi = tid;
        argmax_combine(v, bi, rs[tid + 1024], tid + 1024);
        for (int o = 16; o; o >>= 1) {
            const float ov = __shfl_down_sync(0xffffffffu, v, o);
            const int   oi = __shfl_down_sync(0xffffffffu, bi, o);
            argmax_combine(v, bi, ov, oi);
        }
        if (l == 0) { sval[w] = v; sidx[w] = bi; }
        __syncthreads();
        if (tid < 32) {
            v = sval[tid]; bi = sidx[tid];
            for (int o = 16; o; o >>= 1) {
                const float ov = __shfl_down_sync(0xffffffffu, v, o);
                const int   oi = __shfl_down_sync(0xffffffffu, bi, o);
                argmax_combine(v, bi, ov, oi);
            }
            if (tid == 0) {
                s_cur = bi;
                vis[bi >> 5] |= (1u << (bi & 31));
                g_order[b * NN] = bi;
            }
        }
    }

    for (int step = 1; step < NN; step++) {
        __syncthreads();
        const int cur = s_cur;
        const float* row = g_sim + ((size_t)b * NN + cur) * NN;

        const int j0 = tid;
        float x0 = row[j0];
        if ((vis[j0 >> 5] >> (j0 & 31)) & 1u) x0 = -3.0e38f;
        float v = x0; int bi = j0;

        const int j1 = tid + 1024;
        float x1 = row[j1];
        if ((vis[j1 >> 5] >> (j1 & 31)) & 1u) x1 = -3.0e38f;
        argmax_combine(v, bi, x1, j1);

        for (int o = 16; o; o >>= 1) {
            const float ov = __shfl_down_sync(0xffffffffu, v, o);
            const int   oi = __shfl_down_sync(0xffffffffu, bi, o);
            argmax_combine(v, bi, ov, oi);
        }
        if (l == 0) { sval[w] = v; sidx[w] = bi; }
        __syncthreads();
        if (tid < 32) {
            v = sval[tid]; bi = sidx[tid];
            for (int o = 16; o; o >>= 1) {
                const float ov = __shfl_down_sync(0xffffffffu, v, o);
                const int   oi = __shfl_down_sync(0xffffffffu, bi, o);
                argmax_combine(v, bi, ov, oi);
            }
            if (tid == 0) {
                s_cur = bi;
                vis[bi >> 5] |= (1u << (bi & 31));
                g_order[b * NN + step] = bi;
            }
        }
    }
}

// ---------------- K5: gather reordered features ----------------
__global__ void kreorder(const float* __restrict__ f, float* __restrict__ out) {
    const int b = blockIdx.y, i = blockIdx.x;
    const int src = g_order[b * NN + i];
    const float4* s = (const float4*)(f + ((size_t)b * NN + src) * DD);
    float4* d = (float4*)(out + ((size_t)b * NN + i) * DD);
    d[threadIdx.x] = s[threadIdx.x];
}

__global__ void korder(float* __restrict__ out) {
    const int t = blockIdx.x * blockDim.x + threadIdx.x;
    if (t < BB * NN) out[(size_t)BB * NN * DD + t] = (float)g_order[t];
}

extern "C" void kernel_launch(void* const* d_in, const int* in_sizes, int n_in,
                              void* d_out, int out_size) {
    const float* features = (const float*)d_in[0];
    const float* coords   = (const float*)d_in[1];
    float* out = (float*)d_out;

    knorm<<<BB * NN, 256>>>(features);

    dim3 gg(NTI, NTI, BB);
    kgemm<<<gg, 256>>>(coords);

    krowsum<<<(BB * NN + 255) / 256, 256>>>();

    kgreedy<<<BB, 1024>>>();

    dim3 rg(NN, BB);
    kreorder<<<rg, 192>>>(features, out);

    if ((long long)out_size >= (long long)BB * NN * DD + BB * NN) {
        korder<<<(BB * NN + 255) / 256, 256>>>(out);
    }
}

// round 6
// speedup vs baseline: 1.4669x; 1.4669x over previous
#include <cuda_runtime.h>
#include <math.h>
#include <stdint.h>

#define BB 16
#define NN 2048
#define DD 768
#define NT (NN / 128)               // 16 tiles per dim
#define NPAIR (NT * (NT + 1) / 2)   // 136 upper-tri tile pairs

typedef unsigned long long ull;

// ---- scratch (no dynamic allocation allowed) ----
__device__ float g_fn[(size_t)BB * NN * DD];    // normalized features, 96 MB
__device__ float g_sim[(size_t)BB * NN * NN];   // similarity, 256 MB
__device__ float g_part[(size_t)BB * NN * NT];  // per-tile row-sum partials, 2 MB
__device__ float g_rowsum[BB * NN];
__device__ int   g_order[BB * NN];
__device__ uint16_t g_cand[(size_t)BB * NN * 32];  // top-32 candidate idx per row, 2 MB

__device__ __forceinline__ void argmax_combine(float& v, int& i, float v2, int i2) {
    if (v2 > v || (v2 == v && i2 < i)) { v = v2; i = i2; }
}

__device__ __forceinline__ ull ffma2(ull a, ull b, ull c) {
    ull d;
    asm("fma.rn.f32x2 %0, %1, %2, %3;" : "=l"(d) : "l"(a), "l"(b), "l"(c));
    return d;
}
__device__ __forceinline__ ull pack2(float x, float y) {
    ull r;
    asm("mov.b64 %0, {%1, %2};" : "=l"(r) : "f"(x), "f"(y));
    return r;
}
__device__ __forceinline__ float2 unpack2(ull a) {
    float2 f;
    asm("mov.b64 {%0, %1}, %2;" : "=f"(f.x), "=f"(f.y) : "l"(a));
    return f;
}

// monotone orderable transform for fp32
__device__ __forceinline__ uint32_t okey(float v) {
    uint32_t u = __float_as_uint(v);
    return (u & 0x80000000u) ? ~u : (u | 0x80000000u);
}

// ---------------- K1: normalize feature rows ----------------
__global__ void knorm(const float* __restrict__ f) {
    const int row = blockIdx.x;                       // b*NN + n
    const float* src = f + (size_t)row * DD;
    float s = 0.f;
    for (int i = threadIdx.x; i < DD; i += 256) { float v = src[i]; s += v * v; }
    for (int o = 16; o; o >>= 1) s += __shfl_down_sync(0xffffffffu, s, o);
    __shared__ float red[8];
    const int w = threadIdx.x >> 5, l = threadIdx.x & 31;
    if (l == 0) red[w] = s;
    __syncthreads();
    if (w == 0) {
        s = (l < 8) ? red[l] : 0.f;
        for (int o = 4; o; o >>= 1) s += __shfl_down_sync(0xffffffffu, s, o);
        if (l == 0) red[0] = 1.0f / fmaxf(sqrtf(s), 1e-12f);
    }
    __syncthreads();
    const float scale = red[0];
    float* dst = g_fn + (size_t)row * DD;
    for (int i = threadIdx.x; i < DD; i += 256) dst[i] = src[i] * scale;
}

// ---------------- K2: symmetric SGEMM + spatial + fused rowsum partials ----------------
struct ShMM { float As[16][128]; float Bs[16][128]; };
union ShU {
    ShMM  mm;
    float tb[32][132];
    float cpart[16][132];
};

__global__ void __launch_bounds__(256, 2) kgemm(const float* __restrict__ coords) {
    __shared__ __align__(16) ShU sh;
    __shared__ float2 rc[128];
    __shared__ float2 cc[128];

    int p = blockIdx.x;
    int tmi = 0;
    while (p >= NT - tmi) { p -= NT - tmi; tmi++; }
    const int tni = tmi + p;

    const int b  = blockIdx.z;
    const int tm = tmi * 128;
    const int tn = tni * 128;
    const float*  F = g_fn + (size_t)b * NN * DD;
    const float2* C = (const float2*)(coords + (size_t)b * NN * 2);
    const int tid = threadIdx.x;

    if (tid < 128) rc[tid] = C[tm + tid];
    else           cc[tid - 128] = C[tn + tid - 128];

    const int lr  = tid >> 2;
    const int lc4 = (tid & 3) << 2;
    const int ty  = tid >> 4;
    const int tx  = tid & 15;

    float4 pa[2], pb[2];
#pragma unroll
    for (int r = 0; r < 2; r++) {
        const int row = lr + r * 64;
        pa[r] = *(const float4*)(F + (size_t)(tm + row) * DD + lc4);
        pb[r] = *(const float4*)(F + (size_t)(tn + row) * DD + lc4);
    }

    ull acc2[4][8];
#pragma unroll
    for (int i = 0; i < 4; i++)
#pragma unroll
        for (int j = 0; j < 8; j++) acc2[i][j] = 0ull;

    for (int k0 = 0; k0 < DD; k0 += 16) {
#pragma unroll
        for (int r = 0; r < 2; r++) {
            const int row = lr + r * 64;
            sh.mm.As[lc4 + 0][row] = pa[r].x; sh.mm.As[lc4 + 1][row] = pa[r].y;
            sh.mm.As[lc4 + 2][row] = pa[r].z; sh.mm.As[lc4 + 3][row] = pa[r].w;
            sh.mm.Bs[lc4 + 0][row] = pb[r].x; sh.mm.Bs[lc4 + 1][row] = pb[r].y;
            sh.mm.Bs[lc4 + 2][row] = pb[r].z; sh.mm.Bs[lc4 + 3][row] = pb[r].w;
        }
        __syncthreads();

        if (k0 + 16 < DD) {
#pragma unroll
            for (int r = 0; r < 2; r++) {
                const int row = lr + r * 64;
                pa[r] = *(const float4*)(F + (size_t)(tm + row) * DD + k0 + 16 + lc4);
                pb[r] = *(const float4*)(F + (size_t)(tn + row) * DD + k0 + 16 + lc4);
            }
        }

#pragma unroll
        for (int k = 0; k < 16; k++) {
            const ulonglong2 a01 = *(const ulonglong2*)&sh.mm.As[k][ty * 8];
            const ulonglong2 a23 = *(const ulonglong2*)&sh.mm.As[k][ty * 8 + 4];
            const float4 b0 = *(const float4*)&sh.mm.Bs[k][tx * 8];
            const float4 b1 = *(const float4*)&sh.mm.Bs[k][tx * 8 + 4];
            ull av[4] = { a01.x, a01.y, a23.x, a23.y };
            ull bd[8] = { pack2(b0.x, b0.x), pack2(b0.y, b0.y),
                          pack2(b0.z, b0.z), pack2(b0.w, b0.w),
                          pack2(b1.x, b1.x), pack2(b1.y, b1.y),
                          pack2(b1.z, b1.z), pack2(b1.w, b1.w) };
#pragma unroll
            for (int ip = 0; ip < 4; ip++)
#pragma unroll
                for (int j = 0; j < 8; j++)
                    acc2[ip][j] = ffma2(av[ip], bd[j], acc2[ip][j]);
        }
        __syncthreads();
    }

    float acc[8][8];
#pragma unroll
    for (int ip = 0; ip < 4; ip++)
#pragma unroll
        for (int j = 0; j < 8; j++) {
            const float2 v = unpack2(acc2[ip][j]);
            acc[2 * ip + 0][j] = v.x;
            acc[2 * ip + 1][j] = v.y;
        }

#pragma unroll
    for (int i = 0; i < 8; i++) {
        const float2 r2 = rc[ty * 8 + i];
#pragma unroll
        for (int j = 0; j < 8; j++) {
            const float2 c2 = cc[tx * 8 + j];
            const float dx = r2.x - c2.x, dy = r2.y - c2.y;
            const float sp = expf(-(dx * dx + dy * dy) * (1.0f / 10000.0f));
            acc[i][j] += 0.5f * sp;
        }
    }

    float* S = g_sim + (size_t)b * NN * NN;
#pragma unroll
    for (int i = 0; i < 8; i++) {
        const int gi = tm + ty * 8 + i;
        float4* op = (float4*)(S + (size_t)gi * NN + tn + tx * 8);
        op[0] = make_float4(acc[i][0], acc[i][1], acc[i][2], acc[i][3]);
        op[1] = make_float4(acc[i][4], acc[i][5], acc[i][6], acc[i][7]);
    }

#pragma unroll
    for (int i = 0; i < 8; i++) {
        float s = 0.f;
#pragma unroll
        for (int j = 0; j < 8; j++) s += acc[i][j];
#pragma unroll
        for (int o = 8; o; o >>= 1) s += __shfl_xor_sync(0xffffffffu, s, o);
        if (tx == 0)
            g_part[((size_t)b * NN + tm + ty * 8 + i) * NT + tni] = s;
    }

    if (tmi != tni) {
        float cs[8];
#pragma unroll
        for (int j = 0; j < 8; j++) {
            float s = 0.f;
#pragma unroll
            for (int i = 0; i < 8; i++) s += acc[i][j];
            cs[j] = s;
        }
        __syncthreads();
#pragma unroll
        for (int j = 0; j < 8; j++) sh.cpart[ty][tx * 8 + j] = cs[j];
        __syncthreads();
        if (tid < 128) {
            float s = 0.f;
#pragma unroll
            for (int t = 0; t < 16; t++) s += sh.cpart[t][tid];
            g_part[((size_t)b * NN + tn + tid) * NT + tmi] = s;
        }

#pragma unroll
        for (int c0 = 0; c0 < 128; c0 += 32) {
            __syncthreads();
            if (tx >= (c0 >> 3) && tx < (c0 >> 3) + 4) {
#pragma unroll
                for (int j = 0; j < 8; j++)
#pragma unroll
                    for (int i = 0; i < 8; i++)
                        sh.tb[tx * 8 + j - c0][ty * 8 + i] = acc[i][j];
            }
            __syncthreads();
            const int cc2 = tid >> 3;
            const int seg = (tid & 7) * 16;
            float4* dst = (float4*)(S + (size_t)(tn + c0 + cc2) * NN + tm + seg);
            const float* sr = &sh.tb[cc2][seg];
            dst[0] = make_float4(sr[0],  sr[1],  sr[2],  sr[3]);
            dst[1] = make_float4(sr[4],  sr[5],  sr[6],  sr[7]);
            dst[2] = make_float4(sr[8],  sr[9],  sr[10], sr[11]);
            dst[3] = make_float4(sr[12], sr[13], sr[14], sr[15]);
        }
    }
}

// ---------------- K3: reduce per-tile partials to row sums ----------------
__global__ void krowsum() {
    const int row = blockIdx.x * 256 + threadIdx.x;
    if (row >= BB * NN) return;
    const float* pp = g_part + (size_t)row * NT;
    float s = 0.f;
#pragma unroll
    for (int t = 0; t < NT; t++) s += pp[t];
    g_rowsum[row] = s;
}

// ---------------- K3b: per-row top-32 candidate lists (1 warp / row) ----------------
// key = (okey(val) << 32) | (u32)(~j)  -> max = (max val, tie -> min j)
__global__ void __launch_bounds__(256) ktop() {
    const int row = blockIdx.x * 8 + (threadIdx.x >> 5);   // b*NN + i
    const int lane = threadIdx.x & 31;
    const float4* R4 = (const float4*)(g_sim + (size_t)row * NN);

    ull top[8];
#pragma unroll
    for (int q = 0; q < 8; q++) top[q] = 0ull;

#pragma unroll 4
    for (int i = 0; i < 16; i++) {
        const float4 v = R4[i * 32 + lane];
        const int j0 = i * 128 + lane * 4;
        const float vv[4] = { v.x, v.y, v.z, v.w };
#pragma unroll
        for (int q = 0; q < 4; q++) {
            const ull key = ((ull)okey(vv[q]) << 32) | (uint32_t)(~(j0 + q));
            if (key > top[7]) {
                top[7] = key;
#pragma unroll
                for (int t = 7; t >= 1; t--) {
                    if (top[t] > top[t - 1]) { ull tmp = top[t - 1]; top[t - 1] = top[t]; top[t] = tmp; }
                }
            }
        }
    }

    const ull k7o = top[7];          // original 8th-best (safety bound)
    uint32_t keepj = 0;
    ull w = 0;
#pragma unroll 1
    for (int rnd = 0; rnd < 32; rnd++) {
        const ull best = top[0];
        w = best;
#pragma unroll
        for (int o = 16; o; o >>= 1) {
            const ull ow = __shfl_xor_sync(0xffffffffu, w, o);
            if (ow > w) w = ow;
        }
        const unsigned wm = __ballot_sync(0xffffffffu, best == w);
        const int wl = __ffs(wm) - 1;
        if (lane == wl) {
#pragma unroll
            for (int t = 0; t < 7; t++) top[t] = top[t + 1];
            top[7] = 0ull;
        }
        if (lane == rnd) keepj = ~(uint32_t)w;
    }
    // w == merged 32nd key
    const bool unsafe_row = __any_sync(0xffffffffu, k7o > w);
    g_cand[(size_t)row * 32 + lane] = (uint16_t)keepj;
    if (unsafe_row && lane == 0) g_cand[(size_t)row * 32] = 0xFFFFu;
}

// ---------------- K4: greedy traversal, 1 CTA per batch, candidate fast path ----------------
__global__ void __launch_bounds__(1024) kgreedy() {
    const int b = blockIdx.x;
    __shared__ unsigned vis[NN / 32];
    __shared__ float sval[32];
    __shared__ int   sidx[32];
    __shared__ int   s_cur;
    __shared__ int   s_flag;
    const int tid = threadIdx.x;
    const int w = tid >> 5, l = tid & 31;

    if (tid < NN / 32) vis[tid] = 0u;
    __syncthreads();

    // start node: argmax of row sums (tie -> smallest index)
    {
        const float* rs = g_rowsum + b * NN;
        float v = rs[tid]; int bi = tid;
        argmax_combine(v, bi, rs[tid + 1024], tid + 1024);
        for (int o = 16; o; o >>= 1) {
            const float ov = __shfl_down_sync(0xffffffffu, v, o);
            const int   oi = __shfl_down_sync(0xffffffffu, bi, o);
            argmax_combine(v, bi, ov, oi);
        }
        if (l == 0) { sval[w] = v; sidx[w] = bi; }
        __syncthreads();
        if (tid < 32) {
            v = sval[tid]; bi = sidx[tid];
            for (int o = 16; o; o >>= 1) {
                const float ov = __shfl_down_sync(0xffffffffu, v, o);
                const int   oi = __shfl_down_sync(0xffffffffu, bi, o);
                argmax_combine(v, bi, ov, oi);
            }
            if (tid == 0) {
                s_cur = bi;
                vis[bi >> 5] |= (1u << (bi & 31));
                g_order[b * NN] = bi;
            }
        }
    }

    for (int step = 1; step < NN; step++) {
        __syncthreads();                       // publish vis / s_cur
        if (tid < 32) {
            const uint16_t* cl = g_cand + ((size_t)b * NN + s_cur) * 32;
            const uint16_t ci = cl[tid];
            const uint16_t c0 = (uint16_t)__shfl_sync(0xffffffffu, (int)ci, 0);
            const bool listok = (c0 != 0xFFFFu);
            const bool unv = listok && !((vis[ci >> 5] >> (ci & 31)) & 1u);
            const unsigned m = __ballot_sync(0xffffffffu, unv);
            if (tid == 0) s_flag = (int)m;
            if (m) {
                const int wl2 = __ffs(m) - 1;
                const int j = __shfl_sync(0xffffffffu, (int)ci, wl2);
                if (tid == 0) {
                    s_cur = j;
                    vis[j >> 5] |= (1u << (j & 31));
                    g_order[b * NN + step] = j;
                }
            }
        }
        __syncthreads();
        if (s_flag) continue;

        // fallback: full row scan
        const int cur = s_cur;
        const float* row = g_sim + ((size_t)b * NN + cur) * NN;

        const int j0 = tid;
        float x0 = row[j0];
        if ((vis[j0 >> 5] >> (j0 & 31)) & 1u) x0 = -3.0e38f;
        float v = x0; int bi = j0;

        const int j1 = tid + 1024;
        float x1 = row[j1];
        if ((vis[j1 >> 5] >> (j1 & 31)) & 1u) x1 = -3.0e38f;
        argmax_combine(v, bi, x1, j1);

        for (int o = 16; o; o >>= 1) {
            const float ov = __shfl_down_sync(0xffffffffu, v, o);
            const int   oi = __shfl_down_sync(0xffffffffu, bi, o);
            argmax_combine(v, bi, ov, oi);
        }
        if (l == 0) { sval[w] = v; sidx[w] = bi; }
        __syncthreads();
        if (tid < 32) {
            v = sval[tid]; bi = sidx[tid];
            for (int o = 16; o; o >>= 1) {
                const float ov = __shfl_down_sync(0xffffffffu, v, o);
                const int   oi = __shfl_down_sync(0xffffffffu, bi, o);
                argmax_combine(v, bi, ov, oi);
            }
            if (tid == 0) {
                s_cur = bi;
                vis[bi >> 5] |= (1u << (bi & 31));
                g_order[b * NN + step] = bi;
            }
        }
    }
}

// ---------------- K5: gather reordered features ----------------
__global__ void kreorder(const float* __restrict__ f, float* __restrict__ out) {
    const int b = blockIdx.y, i = blockIdx.x;
    const int src = g_order[b * NN + i];
    const float4* s = (const float4*)(f + ((size_t)b * NN + src) * DD);
    float4* d = (float4*)(out + ((size_t)b * NN + i) * DD);
    d[threadIdx.x] = s[threadIdx.x];
}

__global__ void korder(float* __restrict__ out) {
    const int t = blockIdx.x * blockDim.x + threadIdx.x;
    if (t < BB * NN) out[(size_t)BB * NN * DD + t] = (float)g_order[t];
}

extern "C" void kernel_launch(void* const* d_in, const int* in_sizes, int n_in,
                              void* d_out, int out_size) {
    const float* features = (const float*)d_in[0];
    const float* coords   = (const float*)d_in[1];
    float* out = (float*)d_out;

    knorm<<<BB * NN, 256>>>(features);

    dim3 gg(NPAIR, 1, BB);
    kgemm<<<gg, 256>>>(coords);

    krowsum<<<(BB * NN + 255) / 256, 256>>>();

    ktop<<<(BB * NN) / 8, 256>>>();

    kgreedy<<<BB, 1024>>>();

    dim3 rg(NN, BB);
    kreorder<<<rg, 192>>>(features, out);

    if ((long long)out_size >= (long long)BB * NN * DD + BB * NN) {
        korder<<<(BB * NN + 255) / 256, 256>>>(out);
    }
}

// round 7
// speedup vs baseline: 1.8708x; 1.2753x over previous
#include <cuda_runtime.h>
#include <math.h>
#include <stdint.h>

#define BB 16
#define NN 2048
#define DD 768
#define NT (NN / 128)               // 16 tiles per dim
#define NPAIR (NT * (NT + 1) / 2)   // 136 upper-tri tile pairs

typedef unsigned long long ull;

// ---- scratch (no dynamic allocation allowed) ----
__device__ float g_fn[(size_t)BB * NN * DD];    // normalized features, 96 MB
__device__ float g_sim[(size_t)BB * NN * NN];   // similarity, 256 MB
__device__ float g_rowsum[BB * NN];
__device__ int   g_order[BB * NN];
__device__ uint16_t g_cand[(size_t)BB * NN * 32];  // top-32 candidate idx per row, 2 MB

__device__ __forceinline__ void argmax_combine(float& v, int& i, float v2, int i2) {
    if (v2 > v || (v2 == v && i2 < i)) { v = v2; i = i2; }
}

__device__ __forceinline__ ull ffma2(ull a, ull b, ull c) {
    ull d;
    asm("fma.rn.f32x2 %0, %1, %2, %3;" : "=l"(d) : "l"(a), "l"(b), "l"(c));
    return d;
}
__device__ __forceinline__ ull pack2(float x, float y) {
    ull r;
    asm("mov.b64 %0, {%1, %2};" : "=l"(r) : "f"(x), "f"(y));
    return r;
}
__device__ __forceinline__ float2 unpack2(ull a) {
    float2 f;
    asm("mov.b64 {%0, %1}, %2;" : "=f"(f.x), "=f"(f.y) : "l"(a));
    return f;
}

// monotone orderable transform for fp32 (and inverse)
__device__ __forceinline__ uint32_t okey(float v) {
    uint32_t u = __float_as_uint(v);
    return (u & 0x80000000u) ? ~u : (u | 0x80000000u);
}
__device__ __forceinline__ float unokey(uint32_t k) {
    uint32_t u = (k & 0x80000000u) ? (k ^ 0x80000000u) : ~k;
    return __uint_as_float(u);
}

// ---------------- K1: normalize feature rows ----------------
__global__ void knorm(const float* __restrict__ f) {
    const int row = blockIdx.x;
    const float* src = f + (size_t)row * DD;
    float s = 0.f;
    for (int i = threadIdx.x; i < DD; i += 256) { float v = src[i]; s += v * v; }
    for (int o = 16; o; o >>= 1) s += __shfl_down_sync(0xffffffffu, s, o);
    __shared__ float red[8];
    const int w = threadIdx.x >> 5, l = threadIdx.x & 31;
    if (l == 0) red[w] = s;
    __syncthreads();
    if (w == 0) {
        s = (l < 8) ? red[l] : 0.f;
        for (int o = 4; o; o >>= 1) s += __shfl_down_sync(0xffffffffu, s, o);
        if (l == 0) red[0] = 1.0f / fmaxf(sqrtf(s), 1e-12f);
    }
    __syncthreads();
    const float scale = red[0];
    float* dst = g_fn + (size_t)row * DD;
    for (int i = threadIdx.x; i < DD; i += 256) dst[i] = src[i] * scale;
}

// ---------------- K2: symmetric SGEMM + spatial epilogue ----------------
struct ShMM { float As[16][128]; float Bs[16][128]; };
union ShU {
    ShMM  mm;
    float tb[32][132];
};

__global__ void __launch_bounds__(256, 2) kgemm(const float* __restrict__ coords) {
    __shared__ __align__(16) ShU sh;
    __shared__ float2 rc[128];
    __shared__ float2 cc[128];

    int p = blockIdx.x;
    int tmi = 0;
    while (p >= NT - tmi) { p -= NT - tmi; tmi++; }
    const int tni = tmi + p;

    const int b  = blockIdx.z;
    const int tm = tmi * 128;
    const int tn = tni * 128;
    const float*  F = g_fn + (size_t)b * NN * DD;
    const float2* C = (const float2*)(coords + (size_t)b * NN * 2);
    const int tid = threadIdx.x;

    if (tid < 128) rc[tid] = C[tm + tid];
    else           cc[tid - 128] = C[tn + tid - 128];

    const int lr  = tid >> 2;
    const int lc4 = (tid & 3) << 2;
    const int ty  = tid >> 4;
    const int tx  = tid & 15;

    float4 pa[2], pb[2];
#pragma unroll
    for (int r = 0; r < 2; r++) {
        const int row = lr + r * 64;
        pa[r] = *(const float4*)(F + (size_t)(tm + row) * DD + lc4);
        pb[r] = *(const float4*)(F + (size_t)(tn + row) * DD + lc4);
    }

    ull acc2[4][8];
#pragma unroll
    for (int i = 0; i < 4; i++)
#pragma unroll
        for (int j = 0; j < 8; j++) acc2[i][j] = 0ull;

    for (int k0 = 0; k0 < DD; k0 += 16) {
#pragma unroll
        for (int r = 0; r < 2; r++) {
            const int row = lr + r * 64;
            sh.mm.As[lc4 + 0][row] = pa[r].x; sh.mm.As[lc4 + 1][row] = pa[r].y;
            sh.mm.As[lc4 + 2][row] = pa[r].z; sh.mm.As[lc4 + 3][row] = pa[r].w;
            sh.mm.Bs[lc4 + 0][row] = pb[r].x; sh.mm.Bs[lc4 + 1][row] = pb[r].y;
            sh.mm.Bs[lc4 + 2][row] = pb[r].z; sh.mm.Bs[lc4 + 3][row] = pb[r].w;
        }
        __syncthreads();

        if (k0 + 16 < DD) {
#pragma unroll
            for (int r = 0; r < 2; r++) {
                const int row = lr + r * 64;
                pa[r] = *(const float4*)(F + (size_t)(tm + row) * DD + k0 + 16 + lc4);
                pb[r] = *(const float4*)(F + (size_t)(tn + row) * DD + k0 + 16 + lc4);
            }
        }

#pragma unroll
        for (int k = 0; k < 16; k++) {
            const ulonglong2 a01 = *(const ulonglong2*)&sh.mm.As[k][ty * 8];
            const ulonglong2 a23 = *(const ulonglong2*)&sh.mm.As[k][ty * 8 + 4];
            const float4 b0 = *(const float4*)&sh.mm.Bs[k][tx * 8];
            const float4 b1 = *(const float4*)&sh.mm.Bs[k][tx * 8 + 4];
            ull av[4] = { a01.x, a01.y, a23.x, a23.y };
            ull bd[8] = { pack2(b0.x, b0.x), pack2(b0.y, b0.y),
                          pack2(b0.z, b0.z), pack2(b0.w, b0.w),
                          pack2(b1.x, b1.x), pack2(b1.y, b1.y),
                          pack2(b1.z, b1.z), pack2(b1.w, b1.w) };
#pragma unroll
            for (int ip = 0; ip < 4; ip++)
#pragma unroll
                for (int j = 0; j < 8; j++)
                    acc2[ip][j] = ffma2(av[ip], bd[j], acc2[ip][j]);
        }
        __syncthreads();
    }

    float acc[8][8];
#pragma unroll
    for (int ip = 0; ip < 4; ip++)
#pragma unroll
        for (int j = 0; j < 8; j++) {
            const float2 v = unpack2(acc2[ip][j]);
            acc[2 * ip + 0][j] = v.x;
            acc[2 * ip + 1][j] = v.y;
        }

#pragma unroll
    for (int i = 0; i < 8; i++) {
        const float2 r2 = rc[ty * 8 + i];
#pragma unroll
        for (int j = 0; j < 8; j++) {
            const float2 c2 = cc[tx * 8 + j];
            const float dx = r2.x - c2.x, dy = r2.y - c2.y;
            const float sp = expf(-(dx * dx + dy * dy) * (1.0f / 10000.0f));
            acc[i][j] += 0.5f * sp;
        }
    }

    float* S = g_sim + (size_t)b * NN * NN;
#pragma unroll
    for (int i = 0; i < 8; i++) {
        const int gi = tm + ty * 8 + i;
        float4* op = (float4*)(S + (size_t)gi * NN + tn + tx * 8);
        op[0] = make_float4(acc[i][0], acc[i][1], acc[i][2], acc[i][3]);
        op[1] = make_float4(acc[i][4], acc[i][5], acc[i][6], acc[i][7]);
    }

    if (tmi != tni) {
#pragma unroll
        for (int c0 = 0; c0 < 128; c0 += 32) {
            __syncthreads();
            if (tx >= (c0 >> 3) && tx < (c0 >> 3) + 4) {
#pragma unroll
                for (int j = 0; j < 8; j++)
#pragma unroll
                    for (int i = 0; i < 8; i++)
                        sh.tb[tx * 8 + j - c0][ty * 8 + i] = acc[i][j];
            }
            __syncthreads();
            const int cc2 = tid >> 3;
            const int seg = (tid & 7) * 16;
            float4* dst = (float4*)(S + (size_t)(tn + c0 + cc2) * NN + tm + seg);
            const float* sr = &sh.tb[cc2][seg];
            dst[0] = make_float4(sr[0],  sr[1],  sr[2],  sr[3]);
            dst[1] = make_float4(sr[4],  sr[5],  sr[6],  sr[7]);
            dst[2] = make_float4(sr[8],  sr[9],  sr[10], sr[11]);
            dst[3] = make_float4(sr[12], sr[13], sr[14], sr[15]);
        }
    }
}

// ---------------- K3: per-row top-32 candidates + fused rowsum (1 warp/row) ----------------
// key = (okey(val) << 32) | (u32)(~j)  -> max = (max val, tie -> min j)
__global__ void __launch_bounds__(256) ktop() {
    const int row = blockIdx.x * 8 + (threadIdx.x >> 5);
    const int lane = threadIdx.x & 31;
    const float4* R4 = (const float4*)(g_sim + (size_t)row * NN);

    ull top[8];
#pragma unroll
    for (int q = 0; q < 8; q++) top[q] = 0ull;
    float thr = -3.0e38f;
    float rsum = 0.f;

#pragma unroll 4
    for (int i = 0; i < 16; i++) {
        const float4 v = R4[i * 32 + lane];
        const int j0 = i * 128 + lane * 4;
        const float vv[4] = { v.x, v.y, v.z, v.w };
        rsum += v.x; rsum += v.y; rsum += v.z; rsum += v.w;
#pragma unroll
        for (int q = 0; q < 4; q++) {
            if (vv[q] >= thr) {
                const ull key = ((ull)okey(vv[q]) << 32) | (uint32_t)(~(j0 + q));
                if (key > top[7]) {
                    top[7] = key;
#pragma unroll
                    for (int t = 7; t >= 1; t--) {
                        if (top[t] > top[t - 1]) { ull tmp = top[t - 1]; top[t - 1] = top[t]; top[t] = tmp; }
                    }
                    thr = (top[7] == 0ull) ? -3.0e38f : unokey((uint32_t)(top[7] >> 32));
                }
            }
        }
    }

    // fused deterministic row sum
    {
        float s = rsum;
#pragma unroll
        for (int o = 16; o; o >>= 1) s += __shfl_xor_sync(0xffffffffu, s, o);
        if (lane == 0) g_rowsum[row] = s;
    }

    const ull k7o = top[7];          // original 8th-best (safety bound)
    uint32_t keepj = 0;
    ull w = 0;
#pragma unroll 1
    for (int rnd = 0; rnd < 32; rnd++) {
        const ull best = top[0];
        w = best;
#pragma unroll
        for (int o = 16; o; o >>= 1) {
            const ull ow = __shfl_xor_sync(0xffffffffu, w, o);
            if (ow > w) w = ow;
        }
        const unsigned wm = __ballot_sync(0xffffffffu, best == w);
        const int wl = __ffs(wm) - 1;
        if (lane == wl) {
#pragma unroll
            for (int t = 0; t < 7; t++) top[t] = top[t + 1];
            top[7] = 0ull;
        }
        if (lane == rnd) keepj = ~(uint32_t)w;
    }
    const bool unsafe_row = __any_sync(0xffffffffu, k7o > w);
    g_cand[(size_t)row * 32 + lane] = (uint16_t)keepj;
    if (unsafe_row && lane == 0) g_cand[(size_t)row * 32] = 0xFFFFu;
}

// ---------------- K4: greedy, 1 warp/batch, cand table in smem ----------------
// dynamic smem: [0,131072) cand u16; [131072,139264) order int; [139264,139520) vis
#define GR_CAND 0
#define GR_ORD  131072
#define GR_VIS  139264
#define GR_SMEM 139776

extern __shared__ char gsm[];

__global__ void __launch_bounds__(256) kgreedy() {
    const int b = blockIdx.x;
    const int tid = threadIdx.x;
    const int lane = tid & 31;
    uint16_t* scand = (uint16_t*)(gsm + GR_CAND);
    int*      sord  = (int*)(gsm + GR_ORD);
    unsigned* vis   = (unsigned*)(gsm + GR_VIS);

    __shared__ float sval[8];
    __shared__ int   sidx[8];
    __shared__ int   s_cur;

    // stage candidate table (128 KB) into smem
    {
        const uint4* src = (const uint4*)(g_cand + (size_t)b * NN * 32);
        uint4* dst = (uint4*)scand;
        for (int i = tid; i < NN * 32 / 8; i += 256) dst[i] = src[i];
    }
    if (tid < NN / 32) vis[tid] = 0u;

    // start node: argmax of row sums (256 threads)
    {
        const float* rs = g_rowsum + b * NN;
        float v = -3.4e38f; int bi = 0;
#pragma unroll
        for (int q = 0; q < 8; q++) {
            const int j = q * 256 + tid;
            argmax_combine(v, bi, rs[j], j);
        }
        for (int o = 16; o; o >>= 1) {
            const float ov = __shfl_down_sync(0xffffffffu, v, o);
            const int   oi = __shfl_down_sync(0xffffffffu, bi, o);
            argmax_combine(v, bi, ov, oi);
        }
        if (lane == 0) { sval[tid >> 5] = v; sidx[tid >> 5] = bi; }
    }
    __syncthreads();
    if (tid >= 32) return;            // warp 0 proceeds alone

    {
        float v = sval[0]; int bi = sidx[0];
#pragma unroll
        for (int q = 1; q < 8; q++) argmax_combine(v, bi, sval[q], sidx[q]);
        if (lane == 0) {
            s_cur = bi;
            vis[bi >> 5] |= (1u << (bi & 31));
            sord[0] = bi;
        }
    }
    __syncwarp();

    int cur = s_cur;
    const float* S = g_sim + (size_t)b * NN * NN;

    for (int step = 1; step < NN; step++) {
        const uint16_t ci = scand[cur * 32 + lane];
        const uint16_t c0 = (uint16_t)__shfl_sync(0xffffffffu, (int)ci, 0);
        bool unv = false;
        if (c0 != 0xFFFFu)
            unv = !((vis[ci >> 5] >> (ci & 31)) & 1u);
        const unsigned m = __ballot_sync(0xffffffffu, unv);
        int j;
        if (m) {
            const int wl = __ffs(m) - 1;
            j = __shfl_sync(0xffffffffu, (int)ci, wl);
        } else {
            // fallback: full row scan (warp-only, MLP-deep)
            const float4* R4 = (const float4*)(S + (size_t)cur * NN);
            float v = -3.4e38f; int bi = 0;
#pragma unroll 4
            for (int i = 0; i < 16; i++) {
                const float4 x = R4[i * 32 + lane];
                const int jb = i * 128 + lane * 4;
                const unsigned vb = vis[jb >> 5];
                const float x0 = ((vb >> (jb & 31)) & 1u)       ? -3.0e38f : x.x;
                const float x1 = ((vb >> ((jb + 1) & 31)) & 1u) ? -3.0e38f : x.y;
                const float x2 = ((vb >> ((jb + 2) & 31)) & 1u) ? -3.0e38f : x.z;
                const float x3 = ((vb >> ((jb + 3) & 31)) & 1u) ? -3.0e38f : x.w;
                argmax_combine(v, bi, x0, jb);
                argmax_combine(v, bi, x1, jb + 1);
                argmax_combine(v, bi, x2, jb + 2);
                argmax_combine(v, bi, x3, jb + 3);
            }
#pragma unroll
            for (int o = 16; o; o >>= 1) {
                const float ov = __shfl_down_sync(0xffffffffu, v, o);
                const int   oi = __shfl_down_sync(0xffffffffu, bi, o);
                argmax_combine(v, bi, ov, oi);
            }
            j = __shfl_sync(0xffffffffu, bi, 0);
        }
        if (lane == 0) {
            vis[j >> 5] |= (1u << (j & 31));
            sord[step] = j;
        }
        __syncwarp();
        cur = j;
    }

    // flush order
    for (int i = lane; i < NN; i += 32) g_order[b * NN + i] = sord[i];
}

// ---------------- K5: gather reordered features ----------------
__global__ void kreorder(const float* __restrict__ f, float* __restrict__ out) {
    const int b = blockIdx.y, i = blockIdx.x;
    const int src = g_order[b * NN + i];
    const float4* s = (const float4*)(f + ((size_t)b * NN + src) * DD);
    float4* d = (float4*)(out + ((size_t)b * NN + i) * DD);
    d[threadIdx.x] = s[threadIdx.x];
}

__global__ void korder(float* __restrict__ out) {
    const int t = blockIdx.x * blockDim.x + threadIdx.x;
    if (t < BB * NN) out[(size_t)BB * NN * DD + t] = (float)g_order[t];
}

extern "C" void kernel_launch(void* const* d_in, const int* in_sizes, int n_in,
                              void* d_out, int out_size) {
    const float* features = (const float*)d_in[0];
    const float* coords   = (const float*)d_in[1];
    float* out = (float*)d_out;

    cudaFuncSetAttribute(kgreedy, cudaFuncAttributeMaxDynamicSharedMemorySize, GR_SMEM);

    knorm<<<BB * NN, 256>>>(features);

    dim3 gg(NPAIR, 1, BB);
    kgemm<<<gg, 256>>>(coords);

    ktop<<<(BB * NN) / 8, 256>>>();

    kgreedy<<<BB, 256, GR_SMEM>>>();

    dim3 rg(NN, BB);
    kreorder<<<rg, 192>>>(features, out);

    if ((long long)out_size >= (long long)BB * NN * DD + BB * NN) {
        korder<<<(BB * NN + 255) / 256, 256>>>(out);
    }
}

// round 8
// speedup vs baseline: 1.9012x; 1.0162x over previous
#include <cuda_runtime.h>
#include <math.h>
#include <stdint.h>

#define BB 16
#define NN 2048
#define DD 768
#define NT (NN / 128)               // 16 tiles per dim
#define NPAIR (NT * (NT + 1) / 2)   // 136 upper-tri tile pairs

typedef unsigned long long ull;

// ---- scratch (no dynamic allocation allowed) ----
__device__ float g_fn[(size_t)BB * NN * DD];    // normalized features, 96 MB
__device__ float g_sim[(size_t)BB * NN * NN];   // similarity, 256 MB
__device__ float g_rowsum[BB * NN];
__device__ int   g_order[BB * NN];
__device__ uint16_t g_cand[(size_t)BB * NN * 32];  // top-32 candidate idx per row, 2 MB

__device__ __forceinline__ void argmax_combine(float& v, int& i, float v2, int i2) {
    if (v2 > v || (v2 == v && i2 < i)) { v = v2; i = i2; }
}

__device__ __forceinline__ ull ffma2(ull a, ull b, ull c) {
    ull d;
    asm("fma.rn.f32x2 %0, %1, %2, %3;" : "=l"(d) : "l"(a), "l"(b), "l"(c));
    return d;
}
__device__ __forceinline__ ull pack2(float x, float y) {
    ull r;
    asm("mov.b64 %0, {%1, %2};" : "=l"(r) : "f"(x), "f"(y));
    return r;
}
__device__ __forceinline__ float2 unpack2(ull a) {
    float2 f;
    asm("mov.b64 {%0, %1}, %2;" : "=f"(f.x), "=f"(f.y) : "l"(a));
    return f;
}

// monotone orderable transform for fp32 (and inverse)
__device__ __forceinline__ uint32_t okey(float v) {
    uint32_t u = __float_as_uint(v);
    return (u & 0x80000000u) ? ~u : (u | 0x80000000u);
}
__device__ __forceinline__ float unokey(uint32_t k) {
    uint32_t u = (k & 0x80000000u) ? (k ^ 0x80000000u) : ~k;
    return __uint_as_float(u);
}

// ---------------- K1: normalize feature rows ----------------
__global__ void knorm(const float* __restrict__ f) {
    const int row = blockIdx.x;
    const float* src = f + (size_t)row * DD;
    float s = 0.f;
    for (int i = threadIdx.x; i < DD; i += 256) { float v = src[i]; s += v * v; }
    for (int o = 16; o; o >>= 1) s += __shfl_down_sync(0xffffffffu, s, o);
    __shared__ float red[8];
    const int w = threadIdx.x >> 5, l = threadIdx.x & 31;
    if (l == 0) red[w] = s;
    __syncthreads();
    if (w == 0) {
        s = (l < 8) ? red[l] : 0.f;
        for (int o = 4; o; o >>= 1) s += __shfl_down_sync(0xffffffffu, s, o);
        if (l == 0) red[0] = 1.0f / fmaxf(sqrtf(s), 1e-12f);
    }
    __syncthreads();
    const float scale = red[0];
    float* dst = g_fn + (size_t)row * DD;
    for (int i = threadIdx.x; i < DD; i += 256) dst[i] = src[i] * scale;
}

// ---------------- K2: symmetric SGEMM, double-buffered, + spatial epilogue ----------------
struct ShMM { float As[16][128]; float Bs[16][128]; };    // 16 KB
union ShU {
    ShMM  mm[2];                                          // 32 KB double buffer
    float tb[32][132];
};

__global__ void __launch_bounds__(256, 2) kgemm(const float* __restrict__ coords) {
    __shared__ __align__(16) ShU sh;
    __shared__ float2 rc[128];
    __shared__ float2 cc[128];

    int p = blockIdx.x;
    int tmi = 0;
    while (p >= NT - tmi) { p -= NT - tmi; tmi++; }
    const int tni = tmi + p;

    const int b  = blockIdx.z;
    const int tm = tmi * 128;
    const int tn = tni * 128;
    const float*  F = g_fn + (size_t)b * NN * DD;
    const float2* C = (const float2*)(coords + (size_t)b * NN * 2);
    const int tid = threadIdx.x;

    if (tid < 128) rc[tid] = C[tm + tid];
    else           cc[tid - 128] = C[tn + tid - 128];

    const int lr  = tid >> 2;
    const int lc4 = (tid & 3) << 2;
    const int ty  = tid >> 4;
    const int tx  = tid & 15;

    // load chunk 0 into regs, store to buffer 0
    float4 pa[2], pb[2];
#pragma unroll
    for (int r = 0; r < 2; r++) {
        const int row = lr + r * 64;
        pa[r] = *(const float4*)(F + (size_t)(tm + row) * DD + lc4);
        pb[r] = *(const float4*)(F + (size_t)(tn + row) * DD + lc4);
    }
#pragma unroll
    for (int r = 0; r < 2; r++) {
        const int row = lr + r * 64;
        sh.mm[0].As[lc4 + 0][row] = pa[r].x; sh.mm[0].As[lc4 + 1][row] = pa[r].y;
        sh.mm[0].As[lc4 + 2][row] = pa[r].z; sh.mm[0].As[lc4 + 3][row] = pa[r].w;
        sh.mm[0].Bs[lc4 + 0][row] = pb[r].x; sh.mm[0].Bs[lc4 + 1][row] = pb[r].y;
        sh.mm[0].Bs[lc4 + 2][row] = pb[r].z; sh.mm[0].Bs[lc4 + 3][row] = pb[r].w;
    }
    __syncthreads();

    ull acc2[4][8];
#pragma unroll
    for (int i = 0; i < 4; i++)
#pragma unroll
        for (int j = 0; j < 8; j++) acc2[i][j] = 0ull;

    const int NCH = DD / 16;
#pragma unroll 1
    for (int c = 0; c < NCH; c++) {
        const int s = c & 1;

        // prefetch next chunk from gmem (latency hidden behind FFMA block)
        if (c + 1 < NCH) {
            const int k0n = (c + 1) * 16;
#pragma unroll
            for (int r = 0; r < 2; r++) {
                const int row = lr + r * 64;
                pa[r] = *(const float4*)(F + (size_t)(tm + row) * DD + k0n + lc4);
                pb[r] = *(const float4*)(F + (size_t)(tn + row) * DD + k0n + lc4);
            }
        }

#pragma unroll
        for (int k = 0; k < 16; k++) {
            const ulonglong2 a01 = *(const ulonglong2*)&sh.mm[s].As[k][ty * 8];
            const ulonglong2 a23 = *(const ulonglong2*)&sh.mm[s].As[k][ty * 8 + 4];
            const float4 b0 = *(const float4*)&sh.mm[s].Bs[k][tx * 8];
            const float4 b1 = *(const float4*)&sh.mm[s].Bs[k][tx * 8 + 4];
            ull av[4] = { a01.x, a01.y, a23.x, a23.y };
            ull bd[8] = { pack2(b0.x, b0.x), pack2(b0.y, b0.y),
                          pack2(b0.z, b0.z), pack2(b0.w, b0.w),
                          pack2(b1.x, b1.x), pack2(b1.y, b1.y),
                          pack2(b1.z, b1.z), pack2(b1.w, b1.w) };
#pragma unroll
            for (int ip = 0; ip < 4; ip++)
#pragma unroll
                for (int j = 0; j < 8; j++)
                    acc2[ip][j] = ffma2(av[ip], bd[j], acc2[ip][j]);
        }

        // store next chunk into the other buffer (peers may still read buf s)
        if (c + 1 < NCH) {
            const int so = s ^ 1;
#pragma unroll
            for (int r = 0; r < 2; r++) {
                const int row = lr + r * 64;
                sh.mm[so].As[lc4 + 0][row] = pa[r].x; sh.mm[so].As[lc4 + 1][row] = pa[r].y;
                sh.mm[so].As[lc4 + 2][row] = pa[r].z; sh.mm[so].As[lc4 + 3][row] = pa[r].w;
                sh.mm[so].Bs[lc4 + 0][row] = pb[r].x; sh.mm[so].Bs[lc4 + 1][row] = pb[r].y;
                sh.mm[so].Bs[lc4 + 2][row] = pb[r].z; sh.mm[so].Bs[lc4 + 3][row] = pb[r].w;
            }
        }
        __syncthreads();
    }

    float acc[8][8];
#pragma unroll
    for (int ip = 0; ip < 4; ip++)
#pragma unroll
        for (int j = 0; j < 8; j++) {
            const float2 v = unpack2(acc2[ip][j]);
            acc[2 * ip + 0][j] = v.x;
            acc[2 * ip + 1][j] = v.y;
        }

#pragma unroll
    for (int i = 0; i < 8; i++) {
        const float2 r2 = rc[ty * 8 + i];
#pragma unroll
        for (int j = 0; j < 8; j++) {
            const float2 c2 = cc[tx * 8 + j];
            const float dx = r2.x - c2.x, dy = r2.y - c2.y;
            const float sp = expf(-(dx * dx + dy * dy) * (1.0f / 10000.0f));
            acc[i][j] += 0.5f * sp;
        }
    }

    float* S = g_sim + (size_t)b * NN * NN;
#pragma unroll
    for (int i = 0; i < 8; i++) {
        const int gi = tm + ty * 8 + i;
        float4* op = (float4*)(S + (size_t)gi * NN + tn + tx * 8);
        op[0] = make_float4(acc[i][0], acc[i][1], acc[i][2], acc[i][3]);
        op[1] = make_float4(acc[i][4], acc[i][5], acc[i][6], acc[i][7]);
    }

    if (tmi != tni) {
#pragma unroll
        for (int c0 = 0; c0 < 128; c0 += 32) {
            __syncthreads();
            if (tx >= (c0 >> 3) && tx < (c0 >> 3) + 4) {
#pragma unroll
                for (int j = 0; j < 8; j++)
#pragma unroll
                    for (int i = 0; i < 8; i++)
                        sh.tb[tx * 8 + j - c0][ty * 8 + i] = acc[i][j];
            }
            __syncthreads();
            const int cc2 = tid >> 3;
            const int seg = (tid & 7) * 16;
            float4* dst = (float4*)(S + (size_t)(tn + c0 + cc2) * NN + tm + seg);
            const float* sr = &sh.tb[cc2][seg];
            dst[0] = make_float4(sr[0],  sr[1],  sr[2],  sr[3]);
            dst[1] = make_float4(sr[4],  sr[5],  sr[6],  sr[7]);
            dst[2] = make_float4(sr[8],  sr[9],  sr[10], sr[11]);
            dst[3] = make_float4(sr[12], sr[13], sr[14], sr[15]);
        }
    }
}

// ---------------- K3: per-row top-32 candidates + fused rowsum (1 warp/row) ----------------
__global__ void __launch_bounds__(256) ktop() {
    const int row = blockIdx.x * 8 + (threadIdx.x >> 5);
    const int lane = threadIdx.x & 31;
    const float4* R4 = (const float4*)(g_sim + (size_t)row * NN);

    ull top[8];
#pragma unroll
    for (int q = 0; q < 8; q++) top[q] = 0ull;
    float thr = -3.0e38f;
    float rsum = 0.f;

#pragma unroll 4
    for (int i = 0; i < 16; i++) {
        const float4 v = R4[i * 32 + lane];
        const int j0 = i * 128 + lane * 4;
        const float vv[4] = { v.x, v.y, v.z, v.w };
        rsum += v.x; rsum += v.y; rsum += v.z; rsum += v.w;
#pragma unroll
        for (int q = 0; q < 4; q++) {
            if (vv[q] >= thr) {
                const ull key = ((ull)okey(vv[q]) << 32) | (uint32_t)(~(j0 + q));
                if (key > top[7]) {
                    top[7] = key;
#pragma unroll
                    for (int t = 7; t >= 1; t--) {
                        if (top[t] > top[t - 1]) { ull tmp = top[t - 1]; top[t - 1] = top[t]; top[t] = tmp; }
                    }
                    thr = (top[7] == 0ull) ? -3.0e38f : unokey((uint32_t)(top[7] >> 32));
                }
            }
        }
    }

    {
        float s = rsum;
#pragma unroll
        for (int o = 16; o; o >>= 1) s += __shfl_xor_sync(0xffffffffu, s, o);
        if (lane == 0) g_rowsum[row] = s;
    }

    const ull k7o = top[7];
    uint32_t keepj = 0;
    ull w = 0;
#pragma unroll 1
    for (int rnd = 0; rnd < 32; rnd++) {
        const ull best = top[0];
        w = best;
#pragma unroll
        for (int o = 16; o; o >>= 1) {
            const ull ow = __shfl_xor_sync(0xffffffffu, w, o);
            if (ow > w) w = ow;
        }
        const unsigned wm = __ballot_sync(0xffffffffu, best == w);
        const int wl = __ffs(wm) - 1;
        if (lane == wl) {
#pragma unroll
            for (int t = 0; t < 7; t++) top[t] = top[t + 1];
            top[7] = 0ull;
        }
        if (lane == rnd) keepj = ~(uint32_t)w;
    }
    const bool unsafe_row = __any_sync(0xffffffffu, k7o > w);
    // unsafe rows: ALL entries 0xFFFF -> sentinel index maps to always-visited
    g_cand[(size_t)row * 32 + lane] = unsafe_row ? (uint16_t)0xFFFFu : (uint16_t)keepj;
}

// ---------------- K4: greedy, 1 warp/batch, cand table + extended vis in smem ----------------
// dynamic smem: [0,131072) cand u16; [131072,139264) order int; [139264,147456) vis u32[2048]
#define GR_CAND 0
#define GR_ORD  131072
#define GR_VIS  139264
#define GR_SMEM 147456

extern __shared__ char gsm[];

__global__ void __launch_bounds__(256) kgreedy() {
    const int b = blockIdx.x;
    const int tid = threadIdx.x;
    const int lane = tid & 31;
    uint16_t* scand = (uint16_t*)(gsm + GR_CAND);
    int*      sord  = (int*)(gsm + GR_ORD);
    unsigned* vis   = (unsigned*)(gsm + GR_VIS);

    __shared__ float sval[8];
    __shared__ int   sidx[8];

    // stage candidate table (128 KB) into smem
    {
        const uint4* src = (const uint4*)(g_cand + (size_t)b * NN * 32);
        uint4* dst = (uint4*)scand;
        for (int i = tid; i < NN * 32 / 8; i += 256) dst[i] = src[i];
    }
    // vis: real words zero, shadow words (index >= 64) all-visited
    for (int i = tid; i < 2048; i += 256) vis[i] = (i < NN / 32) ? 0u : 0xFFFFFFFFu;

    // start node: argmax of row sums (256 threads)
    {
        const float* rs = g_rowsum + b * NN;
        float v = -3.4e38f; int bi = 0;
#pragma unroll
        for (int q = 0; q < 8; q++) {
            const int j = q * 256 + tid;
            argmax_combine(v, bi, rs[j], j);
        }
        for (int o = 16; o; o >>= 1) {
            const float ov = __shfl_down_sync(0xffffffffu, v, o);
            const int   oi = __shfl_down_sync(0xffffffffu, bi, o);
            argmax_combine(v, bi, ov, oi);
        }
        if (lane == 0) { sval[tid >> 5] = v; sidx[tid >> 5] = bi; }
    }
    __syncthreads();
    if (tid >= 32) return;            // warp 0 proceeds alone

    int cur;
    {
        float v = sval[0]; int bi = sidx[0];
#pragma unroll
        for (int q = 1; q < 8; q++) argmax_combine(v, bi, sval[q], sidx[q]);
        cur = bi;
        if (lane == 0) {
            vis[bi >> 5] |= (1u << (bi & 31));
            sord[0] = bi;
        }
    }
    __syncwarp();

    const float* S = g_sim + (size_t)b * NN * NN;

    for (int step = 1; step < NN; step++) {
        const int ci = (int)scand[cur * 32 + lane];
        const unsigned vb = vis[ci >> 5];
        const bool unv = !((vb >> (ci & 31)) & 1u);
        const unsigned m = __ballot_sync(0xffffffffu, unv);
        int j;
        if (m) {
            j = __shfl_sync(0xffffffffu, ci, __ffs(m) - 1);
        } else {
            // fallback: full row scan (warp-only, MLP-deep)
            const float4* R4 = (const float4*)(S + (size_t)cur * NN);
            float v = -3.4e38f; int bi = 0;
#pragma unroll 4
            for (int i = 0; i < 16; i++) {
                const float4 x = R4[i * 32 + lane];
                const int jb = i * 128 + lane * 4;
                const unsigned vw = vis[jb >> 5];
                const float x0 = ((vw >> (jb & 31)) & 1u)       ? -3.0e38f : x.x;
                const float x1 = ((vw >> ((jb + 1) & 31)) & 1u) ? -3.0e38f : x.y;
                const float x2 = ((vw >> ((jb + 2) & 31)) & 1u) ? -3.0e38f : x.z;
                const float x3 = ((vw >> ((jb + 3) & 31)) & 1u) ? -3.0e38f : x.w;
                argmax_combine(v, bi, x0, jb);
                argmax_combine(v, bi, x1, jb + 1);
                argmax_combine(v, bi, x2, jb + 2);
                argmax_combine(v, bi, x3, jb + 3);
            }
#pragma unroll
            for (int o = 16; o; o >>= 1) {
                const float ov = __shfl_down_sync(0xffffffffu, v, o);
                const int   oi = __shfl_down_sync(0xffffffffu, bi, o);
                argmax_combine(v, bi, ov, oi);
            }
            j = __shfl_sync(0xffffffffu, bi, 0);
        }
        if (lane == 0) {
            vis[j >> 5] |= (1u << (j & 31));
            sord[step] = j;
        }
        __syncwarp();
        cur = j;
    }

    for (int i = lane; i < NN; i += 32) g_order[b * NN + i] = sord[i];
}

// ---------------- K5: gather reordered features ----------------
__global__ void kreorder(const float* __restrict__ f, float* __restrict__ out) {
    const int b = blockIdx.y, i = blockIdx.x;
    const int src = g_order[b * NN + i];
    const float4* s = (const float4*)(f + ((size_t)b * NN + src) * DD);
    float4* d = (float4*)(out + ((size_t)b * NN + i) * DD);
    d[threadIdx.x] = s[threadIdx.x];
}

__global__ void korder(float* __restrict__ out) {
    const int t = blockIdx.x * blockDim.x + threadIdx.x;
    if (t < BB * NN) out[(size_t)BB * NN * DD + t] = (float)g_order[t];
}

extern "C" void kernel_launch(void* const* d_in, const int* in_sizes, int n_in,
                              void* d_out, int out_size) {
    const float* features = (const float*)d_in[0];
    const float* coords   = (const float*)d_in[1];
    float* out = (float*)d_out;

    cudaFuncSetAttribute(kgreedy, cudaFuncAttributeMaxDynamicSharedMemorySize, GR_SMEM);

    knorm<<<BB * NN, 256>>>(features);

    dim3 gg(NPAIR, 1, BB);
    kgemm<<<gg, 256>>>(coords);

    ktop<<<(BB * NN) / 8, 256>>>();

    kgreedy<<<BB, 256, GR_SMEM>>>();

    dim3 rg(NN, BB);
    kreorder<<<rg, 192>>>(features, out);

    if ((long long)out_size >= (long long)BB * NN * DD + BB * NN) {
        korder<<<(BB * NN + 255) / 256, 256>>>(out);
    }
}

// round 9
// speedup vs baseline: 2.1500x; 1.1308x over previous
#include <cuda_runtime.h>
#include <math.h>
#include <stdint.h>

#define BB 16
#define NN 2048
#define DD 768
#define NT (NN / 128)               // 16 tiles per dim
#define NPAIR (NT * (NT + 1) / 2)   // 136 upper-tri tile pairs

typedef unsigned long long ull;

// ---- scratch (no dynamic allocation allowed) ----
__device__ float g_fn[(size_t)BB * NN * DD];    // normalized features, 96 MB
__device__ float g_sim[(size_t)BB * NN * NN];   // similarity, 256 MB
__device__ float g_rowsum[BB * NN];
__device__ int   g_order[BB * NN];
__device__ uint16_t g_cand[(size_t)BB * NN * 32];  // top-32 candidate idx per row, 2 MB

__device__ __forceinline__ void argmax_combine(float& v, int& i, float v2, int i2) {
    if (v2 > v || (v2 == v && i2 < i)) { v = v2; i = i2; }
}

__device__ __forceinline__ ull ffma2(ull a, ull b, ull c) {
    ull d;
    asm("fma.rn.f32x2 %0, %1, %2, %3;" : "=l"(d) : "l"(a), "l"(b), "l"(c));
    return d;
}
__device__ __forceinline__ ull pack2(float x, float y) {
    ull r;
    asm("mov.b64 %0, {%1, %2};" : "=l"(r) : "f"(x), "f"(y));
    return r;
}
__device__ __forceinline__ float2 unpack2(ull a) {
    float2 f;
    asm("mov.b64 {%0, %1}, %2;" : "=f"(f.x), "=f"(f.y) : "l"(a));
    return f;
}

// monotone orderable transform for fp32 (and inverse)
__device__ __forceinline__ uint32_t okey(float v) {
    uint32_t u = __float_as_uint(v);
    return (u & 0x80000000u) ? ~u : (u | 0x80000000u);
}
__device__ __forceinline__ float unokey(uint32_t k) {
    uint32_t u = (k & 0x80000000u) ? (k ^ 0x80000000u) : ~k;
    return __uint_as_float(u);
}

// B permuted position for conflict-free fragment reads
__device__ __forceinline__ int bpos(int c) {
    const int g = c >> 6, cl = c & 63;
    const int t3 = cl >> 3, jj = cl & 7;
    return g * 64 + (jj >> 2) * 32 + t3 * 4 + (jj & 3);
}

// ---------------- K1: normalize feature rows ----------------
__global__ void knorm(const float* __restrict__ f) {
    const int row = blockIdx.x;
    const float* src = f + (size_t)row * DD;
    float s = 0.f;
    for (int i = threadIdx.x; i < DD; i += 256) { float v = src[i]; s += v * v; }
    for (int o = 16; o; o >>= 1) s += __shfl_down_sync(0xffffffffu, s, o);
    __shared__ float red[8];
    const int w = threadIdx.x >> 5, l = threadIdx.x & 31;
    if (l == 0) red[w] = s;
    __syncthreads();
    if (w == 0) {
        s = (l < 8) ? red[l] : 0.f;
        for (int o = 4; o; o >>= 1) s += __shfl_down_sync(0xffffffffu, s, o);
        if (l == 0) red[0] = 1.0f / fmaxf(sqrtf(s), 1e-12f);
    }
    __syncthreads();
    const float scale = red[0];
    float* dst = g_fn + (size_t)row * DD;
    for (int i = threadIdx.x; i < DD; i += 256) dst[i] = src[i] * scale;
}

// ---------------- K2: symmetric SGEMM, conflict-free smem, + spatial epilogue ----------------
struct ShMM { float As[16][132]; float Bs[16][132]; };    // 16.5 KB
union ShU {
    ShMM  mm[2];                                          // 33 KB double buffer
    float tb[32][132];
};

__global__ void __launch_bounds__(256, 2) kgemm(const float* __restrict__ coords) {
    __shared__ __align__(16) ShU sh;
    __shared__ float2 rc[128];
    __shared__ float2 cc[128];

    int p = blockIdx.x;
    int tmi = 0;
    while (p >= NT - tmi) { p -= NT - tmi; tmi++; }
    const int tni = tmi + p;

    const int b  = blockIdx.z;
    const int tm = tmi * 128;
    const int tn = tni * 128;
    const float*  F = g_fn + (size_t)b * NN * DD;
    const float2* C = (const float2*)(coords + (size_t)b * NN * 2);
    const int tid = threadIdx.x;

    if (tid < 128) rc[tid] = C[tm + tid];
    else           cc[tid - 128] = C[tn + tid - 128];

    // loader indices
    const int lr  = tid >> 2;             // 0..63 (+64)
    const int s4  = (tid & 3) * 4;        // k-seg base 0,4,8,12
    const int bp0 = bpos(lr);
    const int bp1 = bpos(lr + 64);

    // compute indices
    const int wid = tid >> 5, lane = tid & 31;
    const int wm = wid >> 1, wn = wid & 1;
    const int ty3 = lane >> 3, tx3 = lane & 7;
    const int mr = wm * 32 + ty3 * 8;     // row base (8 rows)
    const int nc = wn * 64 + tx3 * 8;     // col base (8 cols)
    const int boff = wn * 64 + tx3 * 4;   // B read offset

    // load chunk 0 into regs, store to buffer 0
    float4 pa[2], pb[2];
#pragma unroll
    for (int r = 0; r < 2; r++) {
        const int row = lr + r * 64;
        pa[r] = *(const float4*)(F + (size_t)(tm + row) * DD + s4);
        pb[r] = *(const float4*)(F + (size_t)(tn + row) * DD + s4);
    }
#pragma unroll
    for (int r = 0; r < 2; r++) {
        const int row = lr + r * 64;
        const int bp = r ? bp1 : bp0;
        sh.mm[0].As[s4 + 0][row] = pa[r].x; sh.mm[0].As[s4 + 1][row] = pa[r].y;
        sh.mm[0].As[s4 + 2][row] = pa[r].z; sh.mm[0].As[s4 + 3][row] = pa[r].w;
        sh.mm[0].Bs[s4 + 0][bp] = pb[r].x;  sh.mm[0].Bs[s4 + 1][bp] = pb[r].y;
        sh.mm[0].Bs[s4 + 2][bp] = pb[r].z;  sh.mm[0].Bs[s4 + 3][bp] = pb[r].w;
    }
    __syncthreads();

    ull acc2[4][8];
#pragma unroll
    for (int i = 0; i < 4; i++)
#pragma unroll
        for (int j = 0; j < 8; j++) acc2[i][j] = 0ull;

    const int NCH = DD / 16;
#pragma unroll 1
    for (int c = 0; c < NCH; c++) {
        const int s = c & 1;

        if (c + 1 < NCH) {
            const int k0n = (c + 1) * 16;
#pragma unroll
            for (int r = 0; r < 2; r++) {
                const int row = lr + r * 64;
                pa[r] = *(const float4*)(F + (size_t)(tm + row) * DD + k0n + s4);
                pb[r] = *(const float4*)(F + (size_t)(tn + row) * DD + k0n + s4);
            }
        }

#pragma unroll
        for (int k = 0; k < 16; k++) {
            const ulonglong2 a01 = *(const ulonglong2*)&sh.mm[s].As[k][mr];
            const ulonglong2 a23 = *(const ulonglong2*)&sh.mm[s].As[k][mr + 4];
            const float4 b0 = *(const float4*)&sh.mm[s].Bs[k][boff];
            const float4 b1 = *(const float4*)&sh.mm[s].Bs[k][boff + 32];
            ull av[4] = { a01.x, a01.y, a23.x, a23.y };
            ull bd[8] = { pack2(b0.x, b0.x), pack2(b0.y, b0.y),
                          pack2(b0.z, b0.z), pack2(b0.w, b0.w),
                          pack2(b1.x, b1.x), pack2(b1.y, b1.y),
                          pack2(b1.z, b1.z), pack2(b1.w, b1.w) };
#pragma unroll
            for (int ip = 0; ip < 4; ip++)
#pragma unroll
                for (int j = 0; j < 8; j++)
                    acc2[ip][j] = ffma2(av[ip], bd[j], acc2[ip][j]);
        }

        if (c + 1 < NCH) {
            const int so = s ^ 1;
#pragma unroll
            for (int r = 0; r < 2; r++) {
                const int row = lr + r * 64;
                const int bp = r ? bp1 : bp0;
                sh.mm[so].As[s4 + 0][row] = pa[r].x; sh.mm[so].As[s4 + 1][row] = pa[r].y;
                sh.mm[so].As[s4 + 2][row] = pa[r].z; sh.mm[so].As[s4 + 3][row] = pa[r].w;
                sh.mm[so].Bs[s4 + 0][bp] = pb[r].x;  sh.mm[so].Bs[s4 + 1][bp] = pb[r].y;
                sh.mm[so].Bs[s4 + 2][bp] = pb[r].z;  sh.mm[so].Bs[s4 + 3][bp] = pb[r].w;
            }
        }
        __syncthreads();
    }

    float acc[8][8];
#pragma unroll
    for (int ip = 0; ip < 4; ip++)
#pragma unroll
        for (int j = 0; j < 8; j++) {
            const float2 v = unpack2(acc2[ip][j]);
            acc[2 * ip + 0][j] = v.x;
            acc[2 * ip + 1][j] = v.y;
        }

#pragma unroll
    for (int i = 0; i < 8; i++) {
        const float2 r2 = rc[mr + i];
#pragma unroll
        for (int j = 0; j < 8; j++) {
            const float2 c2 = cc[nc + j];
            const float dx = r2.x - c2.x, dy = r2.y - c2.y;
            const float sp = expf(-(dx * dx + dy * dy) * (1.0f / 10000.0f));
            acc[i][j] += 0.5f * sp;
        }
    }

    float* S = g_sim + (size_t)b * NN * NN;
#pragma unroll
    for (int i = 0; i < 8; i++) {
        const int gi = tm + mr + i;
        float4* op = (float4*)(S + (size_t)gi * NN + tn + nc);
        op[0] = make_float4(acc[i][0], acc[i][1], acc[i][2], acc[i][3]);
        op[1] = make_float4(acc[i][4], acc[i][5], acc[i][6], acc[i][7]);
    }

    if (tmi != tni) {
#pragma unroll
        for (int c0 = 0; c0 < 128; c0 += 32) {
            __syncthreads();
            if ((nc & ~31) == c0) {
#pragma unroll
                for (int j = 0; j < 8; j++)
#pragma unroll
                    for (int i = 0; i < 8; i++)
                        sh.tb[nc + j - c0][mr + i] = acc[i][j];
            }
            __syncthreads();
            const int cc2 = tid >> 3;
            const int seg = (tid & 7) * 16;
            float4* dst = (float4*)(S + (size_t)(tn + c0 + cc2) * NN + tm + seg);
            const float* sr = &sh.tb[cc2][seg];
            dst[0] = make_float4(sr[0],  sr[1],  sr[2],  sr[3]);
            dst[1] = make_float4(sr[4],  sr[5],  sr[6],  sr[7]);
            dst[2] = make_float4(sr[8],  sr[9],  sr[10], sr[11]);
            dst[3] = make_float4(sr[12], sr[13], sr[14], sr[15]);
        }
    }
}

// ---------------- K3: per-row top-32 candidates + fused rowsum (1 warp/row) ----------------
__global__ void __launch_bounds__(256) ktop() {
    const int row = blockIdx.x * 8 + (threadIdx.x >> 5);
    const int lane = threadIdx.x & 31;
    const float4* R4 = (const float4*)(g_sim + (size_t)row * NN);

    ull top[8];
#pragma unroll
    for (int q = 0; q < 8; q++) top[q] = 0ull;
    float thr = -3.0e38f;
    float rsum = 0.f;

#pragma unroll 4
    for (int i = 0; i < 16; i++) {
        const float4 v = R4[i * 32 + lane];
        const int j0 = i * 128 + lane * 4;
        const float vv[4] = { v.x, v.y, v.z, v.w };
        rsum += v.x; rsum += v.y; rsum += v.z; rsum += v.w;
#pragma unroll
        for (int q = 0; q < 4; q++) {
            if (vv[q] >= thr) {
                const ull key = ((ull)okey(vv[q]) << 32) | (uint32_t)(~(j0 + q));
                if (key > top[7]) {
                    top[7] = key;
#pragma unroll
                    for (int t = 7; t >= 1; t--) {
                        if (top[t] > top[t - 1]) { ull tmp = top[t - 1]; top[t - 1] = top[t]; top[t] = tmp; }
                    }
                    thr = (top[7] == 0ull) ? -3.0e38f : unokey((uint32_t)(top[7] >> 32));
                }
            }
        }
    }

    {
        float s = rsum;
#pragma unroll
        for (int o = 16; o; o >>= 1) s += __shfl_xor_sync(0xffffffffu, s, o);
        if (lane == 0) g_rowsum[row] = s;
    }

    const ull k7o = top[7];
    uint32_t keepj = 0;
    ull w = 0;
#pragma unroll 1
    for (int rnd = 0; rnd < 32; rnd++) {
        const ull best = top[0];
        w = best;
#pragma unroll
        for (int o = 16; o; o >>= 1) {
            const ull ow = __shfl_xor_sync(0xffffffffu, w, o);
            if (ow > w) w = ow;
        }
        const unsigned wm = __ballot_sync(0xffffffffu, best == w);
        const int wl = __ffs(wm) - 1;
        if (lane == wl) {
#pragma unroll
            for (int t = 0; t < 7; t++) top[t] = top[t + 1];
            top[7] = 0ull;
        }
        if (lane == rnd) keepj = ~(uint32_t)w;
    }
    const bool unsafe_row = __any_sync(0xffffffffu, k7o > w);
    g_cand[(size_t)row * 32 + lane] = unsafe_row ? (uint16_t)0xFFFFu : (uint16_t)keepj;
}

// ---------------- K4: greedy, 1 warp/batch, redux + predicated STS ----------------
// dynamic smem: [0,131072) cand u16; [131072,139264) order int; [139264,147456) vis u32[2048]
#define GR_CAND 0
#define GR_ORD  131072
#define GR_VIS  139264
#define GR_SMEM 147456

extern __shared__ char gsm[];

__global__ void __launch_bounds__(256) kgreedy() {
    const int b = blockIdx.x;
    const int tid = threadIdx.x;
    const int lane = tid & 31;
    uint16_t* scand = (uint16_t*)(gsm + GR_CAND);
    int*      sord  = (int*)(gsm + GR_ORD);
    unsigned* vis   = (unsigned*)(gsm + GR_VIS);

    __shared__ float sval[8];
    __shared__ int   sidx[8];

    {
        const uint4* src = (const uint4*)(g_cand + (size_t)b * NN * 32);
        uint4* dst = (uint4*)scand;
        for (int i = tid; i < NN * 32 / 8; i += 256) dst[i] = src[i];
    }
    for (int i = tid; i < 2048; i += 256) vis[i] = (i < NN / 32) ? 0u : 0xFFFFFFFFu;

    {
        const float* rs = g_rowsum + b * NN;
        float v = -3.4e38f; int bi = 0;
#pragma unroll
        for (int q = 0; q < 8; q++) {
            const int j = q * 256 + tid;
            argmax_combine(v, bi, rs[j], j);
        }
        for (int o = 16; o; o >>= 1) {
            const float ov = __shfl_down_sync(0xffffffffu, v, o);
            const int   oi = __shfl_down_sync(0xffffffffu, bi, o);
            argmax_combine(v, bi, ov, oi);
        }
        if (lane == 0) { sval[tid >> 5] = v; sidx[tid >> 5] = bi; }
    }
    __syncthreads();
    if (tid >= 32) return;            // warp 0 proceeds alone

    int cur;
    {
        float v = sval[0]; int bi = sidx[0];
#pragma unroll
        for (int q = 1; q < 8; q++) argmax_combine(v, bi, sval[q], sidx[q]);
        cur = bi;
        if (lane == 0) {
            vis[bi >> 5] |= (1u << (bi & 31));
            sord[0] = bi;
        }
    }
    __syncwarp();

    const float* S = g_sim + (size_t)b * NN * NN;

    for (int step = 1; step < NN; step++) {
        const int ci = (int)scand[cur * 32 + lane];
        const unsigned vw = vis[ci >> 5];
        const bool unv = !((vw >> (ci & 31)) & 1u);
        const unsigned key = unv ? (((unsigned)lane << 16) | (unsigned)ci) : 0xFFFFFFFFu;
        const unsigned kmin = __reduce_min_sync(0xffffffffu, key);
        int j;
        if (kmin != 0xFFFFFFFFu) {
            j = (int)(kmin & 0xFFFFu);
            // winner lane (whose ci == j, vw is j's word) sets the bit, predicated (no branch)
            const unsigned neww = vw | (1u << (j & 31));
            const unsigned waddr = (unsigned)__cvta_generic_to_shared(&vis[j >> 5]);
            asm volatile(
                "{\n\t.reg .pred p;\n\t"
                "setp.eq.u32 p, %0, %1;\n\t"
                "@p st.shared.u32 [%2], %3;\n\t}"
                :: "r"((unsigned)lane), "r"(kmin >> 16), "r"(waddr), "r"(neww) : "memory");
        } else {
            // fallback: full row scan (rare)
            const float4* R4 = (const float4*)(S + (size_t)cur * NN);
            float v = -3.4e38f; int bi = 0;
#pragma unroll 4
            for (int i = 0; i < 16; i++) {
                const float4 x = R4[i * 32 + lane];
                const int jb = i * 128 + lane * 4;
                const unsigned vwf = vis[jb >> 5];
                const float x0 = ((vwf >> (jb & 31)) & 1u)       ? -3.0e38f : x.x;
                const float x1 = ((vwf >> ((jb + 1) & 31)) & 1u) ? -3.0e38f : x.y;
                const float x2 = ((vwf >> ((jb + 2) & 31)) & 1u) ? -3.0e38f : x.z;
                const float x3 = ((vwf >> ((jb + 3) & 31)) & 1u) ? -3.0e38f : x.w;
                argmax_combine(v, bi, x0, jb);
                argmax_combine(v, bi, x1, jb + 1);
                argmax_combine(v, bi, x2, jb + 2);
                argmax_combine(v, bi, x3, jb + 3);
            }
#pragma unroll
            for (int o = 16; o; o >>= 1) {
                const float ov = __shfl_down_sync(0xffffffffu, v, o);
                const int   oi = __shfl_down_sync(0xffffffffu, bi, o);
                argmax_combine(v, bi, ov, oi);
            }
            j = __shfl_sync(0xffffffffu, bi, 0);
            if (lane == 0) vis[j >> 5] |= (1u << (j & 31));
            __syncwarp();
        }
        sord[step] = j;        // same addr+value from all lanes: write-collapses
        cur = j;
    }

    for (int i = lane; i < NN; i += 32) g_order[b * NN + i] = sord[i];
}

// ---------------- K5: gather reordered features ----------------
__global__ void kreorder(const float* __restrict__ f, float* __restrict__ out) {
    const int b = blockIdx.y, i = blockIdx.x;
    const int src = g_order[b * NN + i];
    const float4* s = (const float4*)(f + ((size_t)b * NN + src) * DD);
    float4* d = (float4*)(out + ((size_t)b * NN + i) * DD);
    d[threadIdx.x] = s[threadIdx.x];
}

__global__ void korder(float* __restrict__ out) {
    const int t = blockIdx.x * blockDim.x + threadIdx.x;
    if (t < BB * NN) out[(size_t)BB * NN * DD + t] = (float)g_order[t];
}

extern "C" void kernel_launch(void* const* d_in, const int* in_sizes, int n_in,
                              void* d_out, int out_size) {
    const float* features = (const float*)d_in[0];
    const float* coords   = (const float*)d_in[1];
    float* out = (float*)d_out;

    cudaFuncSetAttribute(kgreedy, cudaFuncAttributeMaxDynamicSharedMemorySize, GR_SMEM);

    knorm<<<BB * NN, 256>>>(features);

    dim3 gg(NPAIR, 1, BB);
    kgemm<<<gg, 256>>>(coords);

    ktop<<<(BB * NN) / 8, 256>>>();

    kgreedy<<<BB, 256, GR_SMEM>>>();

    dim3 rg(NN, BB);
    kreorder<<<rg, 192>>>(features, out);

    if ((long long)out_size >= (long long)BB * NN * DD + BB * NN) {
        korder<<<(BB * NN + 255) / 256, 256>>>(out);
    }
}